// round 4
// baseline (speedup 1.0000x reference)
#include <cuda_runtime.h>
#include <math.h>

#define NTOK 4096
#define D0   1024
#define DI   4096
#define DLAT 64

// 64 MB scratch, reused for both [4096,4096] intermediates (kernels are sequential)
__device__ float  g_h1[(size_t)NTOK * DI];
__device__ double g_acc[3];

__device__ __forceinline__ float gelu_exact(float x) {
    return 0.5f * x * (1.0f + erff(x * 0.70710678118654752f));
}

// ---------------- generic 128x128x8 SGEMM, bias + optional exact GELU ----------------
template<int GELU>
__global__ __launch_bounds__(256) void sgemm_kernel(
    const float* __restrict__ A,   // [M,K] row-major
    const float* __restrict__ B,   // [K,N] row-major
    const float* __restrict__ bias,// [N]
    float* __restrict__ C,         // [M,N]
    int M, int N, int K)
{
    __shared__ float As[8][128];
    __shared__ float Bs[8][128];
    const int tid = threadIdx.x;
    const int tx = tid & 15;
    const int ty = tid >> 4;
    const int bx = blockIdx.x, by = blockIdx.y;

    const float* Ab = A + (size_t)by * 128 * K;
    const float* Bb = B + (size_t)bx * 128;

    const int arow = tid >> 1;
    const int acol = (tid & 1) * 4;
    const int brow = tid >> 5;
    const int bcol = (tid & 31) * 4;

    float acc[8][8];
    #pragma unroll
    for (int i = 0; i < 8; i++)
        #pragma unroll
        for (int j = 0; j < 8; j++) acc[i][j] = 0.f;

    for (int k0 = 0; k0 < K; k0 += 8) {
        float4 av = *(const float4*)(Ab + (size_t)arow * K + k0 + acol);
        As[acol+0][arow] = av.x;
        As[acol+1][arow] = av.y;
        As[acol+2][arow] = av.z;
        As[acol+3][arow] = av.w;
        *(float4*)&Bs[brow][bcol] = *(const float4*)(Bb + (size_t)(k0 + brow) * N + bcol);
        __syncthreads();
        #pragma unroll
        for (int k = 0; k < 8; k++) {
            float4 a0 = *(const float4*)&As[k][ty * 4];
            float4 a1 = *(const float4*)&As[k][64 + ty * 4];
            float4 b0 = *(const float4*)&Bs[k][tx * 4];
            float4 b1 = *(const float4*)&Bs[k][64 + tx * 4];
            float a[8] = {a0.x,a0.y,a0.z,a0.w,a1.x,a1.y,a1.z,a1.w};
            float b[8] = {b0.x,b0.y,b0.z,b0.w,b1.x,b1.y,b1.z,b1.w};
            #pragma unroll
            for (int i = 0; i < 8; i++)
                #pragma unroll
                for (int j = 0; j < 8; j++)
                    acc[i][j] = fmaf(a[i], b[j], acc[i][j]);
        }
        __syncthreads();
    }

    #pragma unroll
    for (int ih = 0; ih < 2; ih++)
      #pragma unroll
      for (int i = 0; i < 4; i++) {
        int row = by * 128 + ih * 64 + ty * 4 + i;
        #pragma unroll
        for (int jh = 0; jh < 2; jh++) {
            int col0 = bx * 128 + jh * 64 + tx * 4;
            float4 v;
            float* pv = &v.x;
            #pragma unroll
            for (int j = 0; j < 4; j++) {
                float t = acc[ih*4 + i][jh*4 + j] + bias[col0 + j];
                pv[j] = GELU ? gelu_exact(t) : t;
            }
            *(float4*)(C + (size_t)row * N + col0) = v;
        }
      }
}

// ---------------- encoder GEMM2 (N=64) fused with LayerNorm over 64 ----------------
__global__ __launch_bounds__(256) void enc2_ln_kernel(
    const float* __restrict__ A,   // [4096, 4096]
    const float* __restrict__ B,   // [4096, 64]
    const float* __restrict__ bias,
    const float* __restrict__ lg, const float* __restrict__ lb,
    float* __restrict__ out)       // [4096, 64]
{
    __shared__ float As[32][33];
    __shared__ float Bs[32][64];
    __shared__ float P[32][65];
    __shared__ float smu[32], srs[32];
    const int tid = threadIdx.x;
    const int tx = tid & 63;       // column
    const int ty = tid >> 6;       // 0..3 (8 rows each)
    const int row0 = blockIdx.x * 32;
    const int ar = tid >> 3;       // 0..31
    const int ac = (tid & 7) * 4;

    float acc[8] = {0.f,0.f,0.f,0.f,0.f,0.f,0.f,0.f};

    for (int k0 = 0; k0 < DI; k0 += 32) {
        float4 av = *(const float4*)(A + (size_t)(row0 + ar) * DI + k0 + ac);
        As[ar][ac+0] = av.x; As[ar][ac+1] = av.y;
        As[ar][ac+2] = av.z; As[ar][ac+3] = av.w;
        #pragma unroll
        for (int l = 0; l < 2; l++) {
            int idx = tid + l * 256;          // 0..511 float4s of 32x64 tile
            int br = idx >> 4, bc = (idx & 15) * 4;
            *(float4*)&Bs[br][bc] = *(const float4*)(B + (size_t)(k0 + br) * DLAT + bc);
        }
        __syncthreads();
        #pragma unroll
        for (int k = 0; k < 32; k++) {
            float bv = Bs[k][tx];
            #pragma unroll
            for (int i = 0; i < 8; i++)
                acc[i] = fmaf(As[ty*8 + i][k], bv, acc[i]);
        }
        __syncthreads();
    }

    #pragma unroll
    for (int i = 0; i < 8; i++)
        P[ty*8 + i][tx] = acc[i] + bias[tx];
    __syncthreads();

    if (tid < 32) {
        float s = 0.f;
        for (int c = 0; c < 64; c++) s += P[tid][c];
        float mu = s * (1.f/64.f);
        float vs = 0.f;
        for (int c = 0; c < 64; c++) { float d = P[tid][c] - mu; vs += d*d; }
        smu[tid] = mu;
        srs[tid] = rsqrtf(vs * (1.f/64.f) + 1e-9f);
    }
    __syncthreads();

    #pragma unroll
    for (int i = 0; i < 8; i++) {
        int r = ty*8 + i;
        out[(size_t)(row0 + r) * DLAT + tx] =
            (P[r][tx] - smu[r]) * srs[r] * lg[tx] + lb[tx];
    }
}

// ---------------- in-place LayerNorm over 1024 ----------------
__global__ __launch_bounds__(256) void ln_inplace_kernel(
    float* __restrict__ x, const float* __restrict__ g, const float* __restrict__ b)
{
    const int row = blockIdx.x;
    float* p = x + (size_t)row * D0;
    const int tid = threadIdx.x;
    __shared__ float red[8];

    float v[4];
    float s = 0.f;
    #pragma unroll
    for (int i = 0; i < 4; i++) { v[i] = p[tid + i*256]; s += v[i]; }
    #pragma unroll
    for (int o = 16; o; o >>= 1) s += __shfl_xor_sync(0xffffffffu, s, o);
    if ((tid & 31) == 0) red[tid >> 5] = s;
    __syncthreads();
    float mu = 0.f;
    #pragma unroll
    for (int w = 0; w < 8; w++) mu += red[w];
    mu *= (1.f/1024.f);
    __syncthreads();

    float ss = 0.f;
    #pragma unroll
    for (int i = 0; i < 4; i++) { float d = v[i] - mu; ss += d*d; }
    #pragma unroll
    for (int o = 16; o; o >>= 1) ss += __shfl_xor_sync(0xffffffffu, ss, o);
    if ((tid & 31) == 0) red[tid >> 5] = ss;
    __syncthreads();
    float var = 0.f;
    #pragma unroll
    for (int w = 0; w < 8; w++) var += red[w];
    var *= (1.f/1024.f);
    float rs = rsqrtf(var + 1e-9f);

    #pragma unroll
    for (int i = 0; i < 4; i++) {
        int c = tid + i*256;
        p[c] = (v[i] - mu) * rs * g[c] + b[c];
    }
}

// ---------------- MMD: sum over 64x64 pair tiles of exp(-|x-y|^2 / 4096) ----------------
__global__ __launch_bounds__(256) void mmd_kernel(
    const float* __restrict__ X, const float* __restrict__ Y, double* __restrict__ acc)
{
    __shared__ float Xs[64][65];
    __shared__ float Ys[64][65];
    const int tid = threadIdx.x;
    const int tx = tid & 15, ty = tid >> 4;
    const int xr0 = blockIdx.y * 64, yr0 = blockIdx.x * 64;

    for (int i = tid; i < 1024; i += 256) {   // 1024 float4s cover both 64x64 tiles
        int r = i >> 4, c = (i & 15) * 4;
        float4 xv = *(const float4*)(X + (size_t)(xr0 + r) * DLAT + c);
        Xs[r][c]   = xv.x; Xs[r][c+1] = xv.y; Xs[r][c+2] = xv.z; Xs[r][c+3] = xv.w;
        float4 yv = *(const float4*)(Y + (size_t)(yr0 + r) * DLAT + c);
        Ys[r][c]   = yv.x; Ys[r][c+1] = yv.y; Ys[r][c+2] = yv.z; Ys[r][c+3] = yv.w;
    }
    __syncthreads();

    float s[4][4];
    #pragma unroll
    for (int i = 0; i < 4; i++)
        #pragma unroll
        for (int j = 0; j < 4; j++) s[i][j] = 0.f;

    for (int k = 0; k < 64; k++) {
        float xv[4], yv[4];
        #pragma unroll
        for (int i = 0; i < 4; i++) xv[i] = Xs[ty*4 + i][k];
        #pragma unroll
        for (int j = 0; j < 4; j++) yv[j] = Ys[tx*4 + j][k];
        #pragma unroll
        for (int i = 0; i < 4; i++)
            #pragma unroll
            for (int j = 0; j < 4; j++) {
                float d = xv[i] - yv[j];
                s[i][j] = fmaf(d, d, s[i][j]);
            }
    }

    float tot = 0.f;
    #pragma unroll
    for (int i = 0; i < 4; i++)
        #pragma unroll
        for (int j = 0; j < 4; j++)
            tot += expf(s[i][j] * (-1.f/4096.f));

    #pragma unroll
    for (int o = 16; o; o >>= 1) tot += __shfl_xor_sync(0xffffffffu, tot, o);
    __shared__ float wsum[8];
    if ((tid & 31) == 0) wsum[tid >> 5] = tot;
    __syncthreads();
    if (tid == 0) {
        float bs = 0.f;
        #pragma unroll
        for (int w = 0; w < 8; w++) bs += wsum[w];
        atomicAdd(acc, (double)bs);
    }
}

__global__ void zero_acc_kernel() {
    if (threadIdx.x < 3) g_acc[threadIdx.x] = 0.0;
}

__global__ void finalize_kernel(float* __restrict__ loss_out) {
    const double inv = 1.0 / ((double)NTOK * (double)NTOK);
    double mmd = (g_acc[0] + g_acc[1] - 2.0 * g_acc[2]) * inv;
    *loss_out = (float)(mmd * 64.0);   // / B * S = /8 * 512
}

extern "C" void kernel_launch(void* const* d_in, const int* in_sizes, int n_in,
                              void* d_out, int out_size)
{
    const float* hidden  = (const float*)d_in[0];
    const float* true_s  = (const float*)d_in[1];
    const float* enc_w1  = (const float*)d_in[2];
    const float* enc_b1  = (const float*)d_in[3];
    const float* enc_w2  = (const float*)d_in[4];
    const float* enc_b2  = (const float*)d_in[5];
    const float* enc_lg  = (const float*)d_in[6];
    const float* enc_lb  = (const float*)d_in[7];
    const float* dec_w1  = (const float*)d_in[8];
    const float* dec_b1  = (const float*)d_in[9];
    const float* dec_w2  = (const float*)d_in[10];
    const float* dec_b2  = (const float*)d_in[11];
    const float* dec_lg  = (const float*)d_in[12];
    const float* dec_lb  = (const float*)d_in[13];

    float* recon  = (float*)d_out;                          // [4096, 1024]
    float* latent = recon + (size_t)NTOK * D0;              // [4096, 64]
    float* loss   = latent + (size_t)NTOK * DLAT;           // [1]

    float*  h1;  cudaGetSymbolAddress((void**)&h1,  g_h1);
    double* acc; cudaGetSymbolAddress((void**)&acc, g_acc);

    zero_acc_kernel<<<1, 32>>>();

    // encoder: GEMM1 + GELU -> h1 [4096,4096]
    sgemm_kernel<1><<<dim3(DI/128, NTOK/128), 256>>>(hidden, enc_w1, enc_b1, h1,
                                                     NTOK, DI, D0);
    // encoder: GEMM2 + LN(64) -> latent
    enc2_ln_kernel<<<NTOK/32, 256>>>(h1, enc_w2, enc_b2, enc_lg, enc_lb, latent);

    // MMD terms (double accumulation)
    mmd_kernel<<<dim3(64, 64), 256>>>(true_s, true_s, acc + 0);
    mmd_kernel<<<dim3(64, 64), 256>>>(latent, latent, acc + 1);
    mmd_kernel<<<dim3(64, 64), 256>>>(true_s, latent, acc + 2);

    // decoder: GEMM1 + GELU -> h1 (reuse)
    sgemm_kernel<1><<<dim3(DI/128, NTOK/128), 256>>>(latent, dec_w1, dec_b1, h1,
                                                     NTOK, DI, DLAT);
    // decoder: GEMM2 (bias only) -> recon (pre-LN)
    sgemm_kernel<0><<<dim3(D0/128, NTOK/128), 256>>>(h1, dec_w2, dec_b2, recon,
                                                     NTOK, D0, DI);
    // LN(1024) in place
    ln_inplace_kernel<<<NTOK, 256>>>(recon, dec_lg, dec_lb);

    finalize_kernel<<<1, 1>>>(loss);
}

// round 10
// speedup vs baseline: 1.8554x; 1.8554x over previous
#include <cuda_runtime.h>
#include <cuda_bf16.h>
#include <math.h>
#include <stdint.h>

#define NTOK 4096
#define D0   1024
#define DI   4096
#define DLAT 64

// ---------------- device scratch (no allocs allowed) ----------------
__device__ float         g_h1 [(size_t)NTOK * DI];          // fp32 encoder hidden
__device__ __nv_bfloat16 g_as [(size_t)NTOK * 3 * D0];      // hidden split  [4096, 3072]  hi|lo|hi
__device__ __nv_bfloat16 g_w1s[(size_t)DI   * 3 * D0];      // enc_w1^T split [4096, 3072] hi|hi|lo
__device__ __nv_bfloat16 g_h1s[(size_t)NTOK * 3 * DI];      // dec hidden split [4096,12288] hi|lo|hi
__device__ __nv_bfloat16 g_w2s[(size_t)D0   * 3 * DI];      // dec_w2^T split [1024,12288] hi|hi|lo
__device__ double        g_acc[3];

__device__ __forceinline__ float gelu_exact(float x) {
    return 0.5f * x * (1.0f + erff(x * 0.70710678118654752f));
}

__device__ __forceinline__ uint32_t smem_to_u32(const void* p) {
    uint32_t a;
    asm("{ .reg .u64 t; cvta.to.shared.u64 t, %1; cvt.u32.u64 %0, t; }" : "=r"(a) : "l"(p));
    return a;
}

#define CP_COMMIT() asm volatile("cp.async.commit_group;" ::: "memory")
#define CP_WAIT(n)  asm volatile("cp.async.wait_group %0;" :: "n"(n) : "memory")

// ---------------- bf16 warp-MMA split GEMM: C[M,N] = A[M,KK] . B[N,KK]^T ----------------
// A rows [hi|lo|hi], B rows [hi|hi|lo] along KK = 3*Kseg. fp32 accum via HMMA.16816.
// 128x128 tile, 256 thr (8 warps 2x4, warp tile 64x32), K-chunk 64 bf16, swizzled smem.

// load one 128x64(bf16) K-major swizzled tile for A and B via cp.async (16B units), 256 thr
__device__ __forceinline__ void load_chunk256(const __nv_bfloat16* __restrict__ Ab,
                                              const __nv_bfloat16* __restrict__ Bb,
                                              int KK, int k0, uint32_t sA, uint32_t sB, int tid) {
    #pragma unroll
    for (int i = 0; i < 4; i++) {
        int unit = tid + (i << 8);      // 0..1023
        int r    = unit >> 3;           // 0..127
        int c16  = unit & 7;            // 0..7 (16B blocks)
        uint32_t off = (uint32_t)(r * 128 + ((c16 * 16) ^ ((r & 7) << 4)));
        const void* srcA = (const void*)(Ab + (size_t)r * KK + k0 + c16 * 8);
        const void* srcB = (const void*)(Bb + (size_t)r * KK + k0 + c16 * 8);
        asm volatile("cp.async.cg.shared.global [%0], [%1], 16;" :: "r"(sA + off), "l"(srcA));
        asm volatile("cp.async.cg.shared.global [%0], [%1], 16;" :: "r"(sB + off), "l"(srcB));
    }
}

#define LDSM_X4(r0,r1,r2,r3,addr) \
    asm volatile("ldmatrix.sync.aligned.m8n8.x4.shared.b16 {%0,%1,%2,%3}, [%4];" \
        : "=r"(r0), "=r"(r1), "=r"(r2), "=r"(r3) : "r"(addr))

#define MMA16816(c0,c1,c2,c3,a0,a1,a2,a3,b0,b1) \
    asm volatile("mma.sync.aligned.m16n8k16.row.col.f32.bf16.bf16.f32 " \
        "{%0,%1,%2,%3}, {%4,%5,%6,%7}, {%8,%9}, {%0,%1,%2,%3};" \
        : "+f"(c0), "+f"(c1), "+f"(c2), "+f"(c3) \
        : "r"(a0), "r"(a1), "r"(a2), "r"(a3), "r"(b0), "r"(b1))

template<int GELU>
__global__ __launch_bounds__(256, 2) void mma_gemm_kernel(
    const __nv_bfloat16* __restrict__ A,
    const __nv_bfloat16* __restrict__ B,
    const float* __restrict__ bias,
    float* __restrict__ C,
    int KK, int Ncols)
{
    extern __shared__ char dsm[];
    uint32_t base = (smem_to_u32(dsm) + 1023) & ~1023u;
    uint32_t sA[2] = { base,         base + 16384 };
    uint32_t sB[2] = { base + 32768, base + 49152 };

    const int tid  = threadIdx.x;
    const int wid  = tid >> 5;
    const int lane = tid & 31;
    const int wm   = wid >> 2;        // 0..1  (m offset 64*wm)
    const int wn   = wid & 3;         // 0..3  (n offset 32*wn)
    const int m0 = blockIdx.y * 128;
    const int n0 = blockIdx.x * 128;
    const __nv_bfloat16* Ab = A + (size_t)m0 * KK;
    const __nv_bfloat16* Bb = B + (size_t)n0 * KK;

    // ldmatrix per-lane geometry
    const int aRow  = wm * 64 + (lane & 15);
    const int aH    = (lane >> 4) & 1;           // +16B half
    const int bRowL = (lane & 7) + ((lane >> 4) << 3);
    const int bH    = (lane >> 3) & 1;

    float acc[4][4][4];
    #pragma unroll
    for (int mi = 0; mi < 4; mi++)
        #pragma unroll
        for (int ni = 0; ni < 4; ni++)
            #pragma unroll
            for (int q = 0; q < 4; q++) acc[mi][ni][q] = 0.f;

    const int NC = KK >> 6;

    load_chunk256(Ab, Bb, KK, 0, sA[0], sB[0], tid);
    CP_COMMIT();

    for (int c = 0; c < NC; c++) {
        const int b = c & 1;
        if (c + 1 < NC) {
            load_chunk256(Ab, Bb, KK, (c + 1) << 6, sA[b ^ 1], sB[b ^ 1], tid);
            CP_COMMIT();
            CP_WAIT(1);
        } else {
            CP_WAIT(0);
        }
        __syncthreads();

        const uint32_t cA = sA[b], cB = sB[b];
        #pragma unroll
        for (int ks = 0; ks < 4; ks++) {
            uint32_t a[4][4];
            #pragma unroll
            for (int mi = 0; mi < 4; mi++) {
                int row = aRow + mi * 16;
                uint32_t addr = cA + row * 128 + (((uint32_t)(ks * 32 + aH * 16)) ^ ((row & 7) << 4));
                LDSM_X4(a[mi][0], a[mi][1], a[mi][2], a[mi][3], addr);
            }
            uint32_t bf[4][2];
            #pragma unroll
            for (int bi = 0; bi < 2; bi++) {
                int row = wn * 32 + bi * 16 + bRowL;
                uint32_t addr = cB + row * 128 + (((uint32_t)(ks * 32 + bH * 16)) ^ ((row & 7) << 4));
                LDSM_X4(bf[bi*2][0], bf[bi*2][1], bf[bi*2+1][0], bf[bi*2+1][1], addr);
            }
            #pragma unroll
            for (int mi = 0; mi < 4; mi++)
                #pragma unroll
                for (int ni = 0; ni < 4; ni++)
                    MMA16816(acc[mi][ni][0], acc[mi][ni][1], acc[mi][ni][2], acc[mi][ni][3],
                             a[mi][0], a[mi][1], a[mi][2], a[mi][3],
                             bf[ni][0], bf[ni][1]);
        }
        __syncthreads();
    }

    // epilogue: frag layout m16n8: {c0,c1} row lane/4, cols 2*(lane%4); {c2,c3} row+8
    #pragma unroll
    for (int ni = 0; ni < 4; ni++) {
        int col = n0 + wn * 32 + ni * 8 + (lane & 3) * 2;
        float b0 = bias[col], b1 = bias[col + 1];
        #pragma unroll
        for (int mi = 0; mi < 4; mi++) {
            int row = m0 + wm * 64 + mi * 16 + (lane >> 2);
            float2 v0, v1;
            v0.x = acc[mi][ni][0] + b0; v0.y = acc[mi][ni][1] + b1;
            v1.x = acc[mi][ni][2] + b0; v1.y = acc[mi][ni][3] + b1;
            if (GELU) {
                v0.x = gelu_exact(v0.x); v0.y = gelu_exact(v0.y);
                v1.x = gelu_exact(v1.x); v1.y = gelu_exact(v1.y);
            }
            *(float2*)(C + (size_t)row * Ncols + col)       = v0;
            *(float2*)(C + (size_t)(row + 8) * Ncols + col) = v1;
        }
    }
}

// ---------------- conversion kernels ----------------
// activations: x[M,Kseg] fp32 -> o[M,3*Kseg] bf16 (hi|lo|hi)
__global__ void split_act_kernel(const float* __restrict__ x, __nv_bfloat16* __restrict__ o, int Kseg) {
    int r = blockIdx.y;
    int c = blockIdx.x * 256 + threadIdx.x;
    float v = x[(size_t)r * Kseg + c];
    __nv_bfloat16 hi = __float2bfloat16(v);
    __nv_bfloat16 lo = __float2bfloat16(v - __bfloat162float(hi));
    size_t b = (size_t)r * 3 * Kseg;
    o[b + c] = hi;
    o[b + Kseg + c] = lo;
    o[b + 2 * Kseg + c] = hi;
}

// weights: W[K,N] fp32 -> o[N,3K] bf16 (hi|hi|lo), transposed
__global__ void wsplit_kernel(const float* __restrict__ W, __nv_bfloat16* __restrict__ o, int K, int N) {
    __shared__ float t[32][33];
    int n0 = blockIdx.x * 32, k0 = blockIdx.y * 32;
    int tx = threadIdx.x, ty = threadIdx.y;   // 32 x 8
    #pragma unroll
    for (int i = 0; i < 4; i++)
        t[ty + i * 8][tx] = W[(size_t)(k0 + ty + i * 8) * N + n0 + tx];
    __syncthreads();
    #pragma unroll
    for (int i = 0; i < 4; i++) {
        int n = n0 + ty + i * 8;
        float v = t[tx][ty + i * 8];
        __nv_bfloat16 hi = __float2bfloat16(v);
        __nv_bfloat16 lo = __float2bfloat16(v - __bfloat162float(hi));
        size_t b = (size_t)n * 3 * K;
        o[b + k0 + tx] = hi;
        o[b + K + k0 + tx] = hi;
        o[b + 2 * K + k0 + tx] = lo;
    }
}

// ---------------- decoder GEMM1 (K=64) fp32 FMA, GELU, split-bf16 output ----------------
__global__ __launch_bounds__(256) void sgemm_split_kernel(
    const float* __restrict__ A,   // [M,K]
    const float* __restrict__ B,   // [K,N]
    const float* __restrict__ bias,
    __nv_bfloat16* __restrict__ Cs,// [M, 3*Kout] hi|lo|hi
    int M, int N, int K, int Kout)
{
    __shared__ float As[8][128];
    __shared__ float Bs[8][128];
    const int tid = threadIdx.x;
    const int tx = tid & 15;
    const int ty = tid >> 4;
    const int bx = blockIdx.x, by = blockIdx.y;

    const float* Abp = A + (size_t)by * 128 * K;
    const float* Bbp = B + (size_t)bx * 128;

    const int arow = tid >> 1;
    const int acol = (tid & 1) * 4;
    const int brow = tid >> 5;
    const int bcol = (tid & 31) * 4;

    float acc[8][8];
    #pragma unroll
    for (int i = 0; i < 8; i++)
        #pragma unroll
        for (int j = 0; j < 8; j++) acc[i][j] = 0.f;

    for (int k0 = 0; k0 < K; k0 += 8) {
        float4 av = *(const float4*)(Abp + (size_t)arow * K + k0 + acol);
        As[acol+0][arow] = av.x; As[acol+1][arow] = av.y;
        As[acol+2][arow] = av.z; As[acol+3][arow] = av.w;
        *(float4*)&Bs[brow][bcol] = *(const float4*)(Bbp + (size_t)(k0 + brow) * N + bcol);
        __syncthreads();
        #pragma unroll
        for (int k = 0; k < 8; k++) {
            float4 a0 = *(const float4*)&As[k][ty * 4];
            float4 a1 = *(const float4*)&As[k][64 + ty * 4];
            float4 b0 = *(const float4*)&Bs[k][tx * 4];
            float4 b1 = *(const float4*)&Bs[k][64 + tx * 4];
            float a[8] = {a0.x,a0.y,a0.z,a0.w,a1.x,a1.y,a1.z,a1.w};
            float b[8] = {b0.x,b0.y,b0.z,b0.w,b1.x,b1.y,b1.z,b1.w};
            #pragma unroll
            for (int i = 0; i < 8; i++)
                #pragma unroll
                for (int j = 0; j < 8; j++)
                    acc[i][j] = fmaf(a[i], b[j], acc[i][j]);
        }
        __syncthreads();
    }

    #pragma unroll
    for (int ih = 0; ih < 2; ih++)
      #pragma unroll
      for (int i = 0; i < 4; i++) {
        int row = by * 128 + ih * 64 + ty * 4 + i;
        size_t rb = (size_t)row * 3 * Kout;
        #pragma unroll
        for (int jh = 0; jh < 2; jh++) {
            int col0 = bx * 128 + jh * 64 + tx * 4;
            __nv_bfloat16 hv[4], lv[4];
            #pragma unroll
            for (int j = 0; j < 4; j++) {
                float t = gelu_exact(acc[ih*4 + i][jh*4 + j] + bias[col0 + j]);
                hv[j] = __float2bfloat16(t);
                lv[j] = __float2bfloat16(t - __bfloat162float(hv[j]));
            }
            *(uint2*)(Cs + rb + col0)            = *(uint2*)hv;
            *(uint2*)(Cs + rb + Kout + col0)     = *(uint2*)lv;
            *(uint2*)(Cs + rb + 2 * Kout + col0) = *(uint2*)hv;
        }
      }
}

// ---------------- encoder GEMM2 (N=64) fused with LayerNorm over 64 ----------------
__global__ __launch_bounds__(256) void enc2_ln_kernel(
    const float* __restrict__ A,   // [4096, 4096]
    const float* __restrict__ B,   // [4096, 64]
    const float* __restrict__ bias,
    const float* __restrict__ lg, const float* __restrict__ lb,
    float* __restrict__ out)       // [4096, 64]
{
    __shared__ float As[32][33];
    __shared__ float Bs[32][64];
    __shared__ float P[32][65];
    __shared__ float smu[32], srs[32];
    const int tid = threadIdx.x;
    const int tx = tid & 63;
    const int ty = tid >> 6;
    const int row0 = blockIdx.x * 32;
    const int ar = tid >> 3;
    const int ac = (tid & 7) * 4;

    float acc[8] = {0.f,0.f,0.f,0.f,0.f,0.f,0.f,0.f};

    for (int k0 = 0; k0 < DI; k0 += 32) {
        float4 av = *(const float4*)(A + (size_t)(row0 + ar) * DI + k0 + ac);
        As[ar][ac+0] = av.x; As[ar][ac+1] = av.y;
        As[ar][ac+2] = av.z; As[ar][ac+3] = av.w;
        #pragma unroll
        for (int l = 0; l < 2; l++) {
            int idx = tid + l * 256;
            int br = idx >> 4, bc = (idx & 15) * 4;
            *(float4*)&Bs[br][bc] = *(const float4*)(B + (size_t)(k0 + br) * DLAT + bc);
        }
        __syncthreads();
        #pragma unroll
        for (int k = 0; k < 32; k++) {
            float bv = Bs[k][tx];
            #pragma unroll
            for (int i = 0; i < 8; i++)
                acc[i] = fmaf(As[ty*8 + i][k], bv, acc[i]);
        }
        __syncthreads();
    }

    #pragma unroll
    for (int i = 0; i < 8; i++)
        P[ty*8 + i][tx] = acc[i] + bias[tx];
    __syncthreads();

    if (tid < 32) {
        float s = 0.f;
        for (int c = 0; c < 64; c++) s += P[tid][c];
        float mu = s * (1.f/64.f);
        float vs = 0.f;
        for (int c = 0; c < 64; c++) { float d = P[tid][c] - mu; vs += d*d; }
        smu[tid] = mu;
        srs[tid] = rsqrtf(vs * (1.f/64.f) + 1e-9f);
    }
    __syncthreads();

    #pragma unroll
    for (int i = 0; i < 8; i++) {
        int r = ty*8 + i;
        out[(size_t)(row0 + r) * DLAT + tx] =
            (P[r][tx] - smu[r]) * srs[r] * lg[tx] + lb[tx];
    }
}

// ---------------- in-place LayerNorm over 1024 ----------------
__global__ __launch_bounds__(256) void ln_inplace_kernel(
    float* __restrict__ x, const float* __restrict__ g, const float* __restrict__ b)
{
    const int row = blockIdx.x;
    float* p = x + (size_t)row * D0;
    const int tid = threadIdx.x;
    __shared__ float red[8];

    float v[4];
    float s = 0.f;
    #pragma unroll
    for (int i = 0; i < 4; i++) { v[i] = p[tid + i*256]; s += v[i]; }
    #pragma unroll
    for (int o = 16; o; o >>= 1) s += __shfl_xor_sync(0xffffffffu, s, o);
    if ((tid & 31) == 0) red[tid >> 5] = s;
    __syncthreads();
    float mu = 0.f;
    #pragma unroll
    for (int w = 0; w < 8; w++) mu += red[w];
    mu *= (1.f/1024.f);
    __syncthreads();

    float ss = 0.f;
    #pragma unroll
    for (int i = 0; i < 4; i++) { float d = v[i] - mu; ss += d*d; }
    #pragma unroll
    for (int o = 16; o; o >>= 1) ss += __shfl_xor_sync(0xffffffffu, ss, o);
    if ((tid & 31) == 0) red[tid >> 5] = ss;
    __syncthreads();
    float var = 0.f;
    #pragma unroll
    for (int w = 0; w < 8; w++) var += red[w];
    var *= (1.f/1024.f);
    float rs = rsqrtf(var + 1e-9f);

    #pragma unroll
    for (int i = 0; i < 4; i++) {
        int c = tid + i*256;
        p[c] = (v[i] - mu) * rs * g[c] + b[c];
    }
}

// ---------------- MMD ----------------
__global__ __launch_bounds__(256) void mmd_kernel(
    const float* __restrict__ X, const float* __restrict__ Y, double* __restrict__ acc)
{
    __shared__ float Xs[64][65];
    __shared__ float Ys[64][65];
    const int tid = threadIdx.x;
    const int tx = tid & 15, ty = tid >> 4;
    const int xr0 = blockIdx.y * 64, yr0 = blockIdx.x * 64;

    for (int i = tid; i < 1024; i += 256) {
        int r = i >> 4, c = (i & 15) * 4;
        float4 xv = *(const float4*)(X + (size_t)(xr0 + r) * DLAT + c);
        Xs[r][c]   = xv.x; Xs[r][c+1] = xv.y; Xs[r][c+2] = xv.z; Xs[r][c+3] = xv.w;
        float4 yv = *(const float4*)(Y + (size_t)(yr0 + r) * DLAT + c);
        Ys[r][c]   = yv.x; Ys[r][c+1] = yv.y; Ys[r][c+2] = yv.z; Ys[r][c+3] = yv.w;
    }
    __syncthreads();

    float s[4][4];
    #pragma unroll
    for (int i = 0; i < 4; i++)
        #pragma unroll
        for (int j = 0; j < 4; j++) s[i][j] = 0.f;

    for (int k = 0; k < 64; k++) {
        float xv[4], yv[4];
        #pragma unroll
        for (int i = 0; i < 4; i++) xv[i] = Xs[ty*4 + i][k];
        #pragma unroll
        for (int j = 0; j < 4; j++) yv[j] = Ys[tx*4 + j][k];
        #pragma unroll
        for (int i = 0; i < 4; i++)
            #pragma unroll
            for (int j = 0; j < 4; j++) {
                float d = xv[i] - yv[j];
                s[i][j] = fmaf(d, d, s[i][j]);
            }
    }

    float tot = 0.f;
    #pragma unroll
    for (int i = 0; i < 4; i++)
        #pragma unroll
        for (int j = 0; j < 4; j++)
            tot += __expf(s[i][j] * (-1.f/4096.f));

    #pragma unroll
    for (int o = 16; o; o >>= 1) tot += __shfl_xor_sync(0xffffffffu, tot, o);
    __shared__ float wsum[8];
    if ((tid & 31) == 0) wsum[tid >> 5] = tot;
    __syncthreads();
    if (tid == 0) {
        float bs = 0.f;
        #pragma unroll
        for (int w = 0; w < 8; w++) bs += wsum[w];
        atomicAdd(acc, (double)bs);
    }
}

__global__ void zero_acc_kernel() {
    if (threadIdx.x < 3) g_acc[threadIdx.x] = 0.0;
}

__global__ void finalize_kernel(float* __restrict__ loss_out) {
    const double inv = 1.0 / ((double)NTOK * (double)NTOK);
    double mmd = (g_acc[0] + g_acc[1] - 2.0 * g_acc[2]) * inv;
    *loss_out = (float)(mmd * 64.0);
}

extern "C" void kernel_launch(void* const* d_in, const int* in_sizes, int n_in,
                              void* d_out, int out_size)
{
    const float* hidden  = (const float*)d_in[0];
    const float* true_s  = (const float*)d_in[1];
    const float* enc_w1  = (const float*)d_in[2];
    const float* enc_b1  = (const float*)d_in[3];
    const float* enc_w2  = (const float*)d_in[4];
    const float* enc_b2  = (const float*)d_in[5];
    const float* enc_lg  = (const float*)d_in[6];
    const float* enc_lb  = (const float*)d_in[7];
    const float* dec_w1  = (const float*)d_in[8];
    const float* dec_b1  = (const float*)d_in[9];
    const float* dec_w2  = (const float*)d_in[10];
    const float* dec_b2  = (const float*)d_in[11];
    const float* dec_lg  = (const float*)d_in[12];
    const float* dec_lb  = (const float*)d_in[13];

    float* recon  = (float*)d_out;                          // [4096, 1024]
    float* latent = recon + (size_t)NTOK * D0;              // [4096, 64]
    float* loss   = latent + (size_t)NTOK * DLAT;           // [1]

    float*         h1;  cudaGetSymbolAddress((void**)&h1,  g_h1);
    __nv_bfloat16* as;  cudaGetSymbolAddress((void**)&as,  g_as);
    __nv_bfloat16* w1s; cudaGetSymbolAddress((void**)&w1s, g_w1s);
    __nv_bfloat16* h1s; cudaGetSymbolAddress((void**)&h1s, g_h1s);
    __nv_bfloat16* w2s; cudaGetSymbolAddress((void**)&w2s, g_w2s);
    double*        acc; cudaGetSymbolAddress((void**)&acc, g_acc);

    const int TC_SMEM = 66560;   // 1KB align pad + 2 stages x (16KB A + 16KB B)
    (void)cudaFuncSetAttribute(mma_gemm_kernel<1>, cudaFuncAttributeMaxDynamicSharedMemorySize, TC_SMEM);
    (void)cudaFuncSetAttribute(mma_gemm_kernel<0>, cudaFuncAttributeMaxDynamicSharedMemorySize, TC_SMEM);

    zero_acc_kernel<<<1, 32>>>();

    // --- splits for encoder GEMM1 ---
    split_act_kernel<<<dim3(D0/256, NTOK), 256>>>(hidden, as, D0);
    wsplit_kernel<<<dim3(DI/32, D0/32), dim3(32, 8)>>>(enc_w1, w1s, D0, DI);

    // encoder GEMM1 (HMMA bf16-split, GELU) -> h1 fp32 [4096, 4096]
    mma_gemm_kernel<1><<<dim3(DI/128, NTOK/128), 256, TC_SMEM>>>(as, w1s, enc_b1, h1,
                                                                 3 * D0, DI);

    // encoder GEMM2 + LN(64) -> latent fp32
    enc2_ln_kernel<<<NTOK/32, 256>>>(h1, enc_w2, enc_b2, enc_lg, enc_lb, latent);

    // MMD terms
    mmd_kernel<<<dim3(64, 64), 256>>>(true_s, true_s, acc + 0);
    mmd_kernel<<<dim3(64, 64), 256>>>(latent, latent, acc + 1);
    mmd_kernel<<<dim3(64, 64), 256>>>(true_s, latent, acc + 2);

    // decoder GEMM1 (fp32 FMA, K=64) + GELU -> split bf16 h1s [4096, 12288]
    sgemm_split_kernel<<<dim3(DI/128, NTOK/128), 256>>>(latent, dec_w1, dec_b1, h1s,
                                                        NTOK, DI, DLAT, DI);

    // decoder weight split
    wsplit_kernel<<<dim3(D0/32, DI/32), dim3(32, 8)>>>(dec_w2, w2s, DI, D0);

    // decoder GEMM2 (HMMA bf16-split, bias only) -> recon fp32 [4096, 1024]
    mma_gemm_kernel<0><<<dim3(D0/128, NTOK/128), 256, TC_SMEM>>>(h1s, w2s, dec_b2, recon,
                                                                 3 * DI, D0);

    // LN(1024) in place
    ln_inplace_kernel<<<NTOK, 256>>>(recon, dec_lg, dec_lb);

    finalize_kernel<<<1, 1>>>(loss);
}

// round 14
// speedup vs baseline: 2.2856x; 1.2319x over previous
#include <cuda_runtime.h>
#include <cuda_bf16.h>
#include <math.h>
#include <stdint.h>

#define NTOK 4096
#define D0   1024
#define DI   4096
#define DLAT 64

// ---------------- device scratch (no allocs allowed) ----------------
__device__ float         g_h1 [(size_t)NTOK * DI];          // fp32 encoder hidden
__device__ __nv_bfloat16 g_as [(size_t)NTOK * 3 * D0];      // hidden split  [4096, 3072]  hi|lo|hi
__device__ __nv_bfloat16 g_w1s[(size_t)DI   * 3 * D0];      // enc_w1^T split [4096, 3072] hi|hi|lo
__device__ __nv_bfloat16 g_h1s[(size_t)NTOK * 3 * DI];      // dec hidden split [4096,12288] hi|lo|hi
__device__ __nv_bfloat16 g_w2s[(size_t)D0   * 3 * DI];      // dec_w2^T split [1024,12288] hi|hi|lo
// MMD splits: [4096, 192] A-form (hi|lo|hi) and B-form (hi|hi|lo) + fp32 row norms
__device__ __nv_bfloat16 g_tsA[(size_t)NTOK * 3 * DLAT];
__device__ __nv_bfloat16 g_tsB[(size_t)NTOK * 3 * DLAT];
__device__ __nv_bfloat16 g_laA[(size_t)NTOK * 3 * DLAT];
__device__ __nv_bfloat16 g_laB[(size_t)NTOK * 3 * DLAT];
__device__ float         g_tn [NTOK];
__device__ float         g_ln [NTOK];
__device__ double        g_acc[3];

__device__ __forceinline__ float gelu_exact(float x) {
    return 0.5f * x * (1.0f + erff(x * 0.70710678118654752f));
}

__device__ __forceinline__ uint32_t smem_to_u32(const void* p) {
    uint32_t a;
    asm("{ .reg .u64 t; cvta.to.shared.u64 t, %1; cvt.u32.u64 %0, t; }" : "=r"(a) : "l"(p));
    return a;
}

#define CP_COMMIT() asm volatile("cp.async.commit_group;" ::: "memory")
#define CP_WAIT(n)  asm volatile("cp.async.wait_group %0;" :: "n"(n) : "memory")

// load one 128x64(bf16) K-major swizzled tile for A and B via cp.async (16B units), 256 thr
__device__ __forceinline__ void load_chunk256(const __nv_bfloat16* __restrict__ Ab,
                                              const __nv_bfloat16* __restrict__ Bb,
                                              int KK, int k0, uint32_t sA, uint32_t sB, int tid) {
    #pragma unroll
    for (int i = 0; i < 4; i++) {
        int unit = tid + (i << 8);      // 0..1023
        int r    = unit >> 3;           // 0..127
        int c16  = unit & 7;            // 0..7 (16B blocks)
        uint32_t off = (uint32_t)(r * 128 + ((c16 * 16) ^ ((r & 7) << 4)));
        const void* srcA = (const void*)(Ab + (size_t)r * KK + k0 + c16 * 8);
        const void* srcB = (const void*)(Bb + (size_t)r * KK + k0 + c16 * 8);
        asm volatile("cp.async.cg.shared.global [%0], [%1], 16;" :: "r"(sA + off), "l"(srcA));
        asm volatile("cp.async.cg.shared.global [%0], [%1], 16;" :: "r"(sB + off), "l"(srcB));
    }
}

#define LDSM_X4(r0,r1,r2,r3,addr) \
    asm volatile("ldmatrix.sync.aligned.m8n8.x4.shared.b16 {%0,%1,%2,%3}, [%4];" \
        : "=r"(r0), "=r"(r1), "=r"(r2), "=r"(r3) : "r"(addr))

#define MMA16816(c0,c1,c2,c3,a0,a1,a2,a3,b0,b1) \
    asm volatile("mma.sync.aligned.m16n8k16.row.col.f32.bf16.bf16.f32 " \
        "{%0,%1,%2,%3}, {%4,%5,%6,%7}, {%8,%9}, {%0,%1,%2,%3};" \
        : "+f"(c0), "+f"(c1), "+f"(c2), "+f"(c3) \
        : "r"(a0), "r"(a1), "r"(a2), "r"(a3), "r"(b0), "r"(b1))

// Shared mainloop: 128x128 tile, 8 warps (2x4), warp tile 64x32, 3-stage cp.async
// pipeline, single __syncthreads per chunk. 96KB smem (3 x (16KB A + 16KB B)).
__device__ __forceinline__ void mma_mainloop(
    const __nv_bfloat16* __restrict__ Ab, const __nv_bfloat16* __restrict__ Bb,
    int KK, int NC, const uint32_t* sA, const uint32_t* sB,
    int tid, int aRow, int aH, int bRowL, int bH, int wn,
    float acc[4][4][4])
{
    load_chunk256(Ab, Bb, KK, 0, sA[0], sB[0], tid);
    CP_COMMIT();
    if (NC > 1) {
        load_chunk256(Ab, Bb, KK, 64, sA[1], sB[1], tid);
        CP_COMMIT();
    }

    for (int c = 0; c < NC; c++) {
        if (c + 1 < NC) { CP_WAIT(1); } else { CP_WAIT(0); }
        __syncthreads();
        if (c + 2 < NC) {
            int s = (c + 2) % 3;
            load_chunk256(Ab, Bb, KK, (c + 2) << 6, sA[s], sB[s], tid);
            CP_COMMIT();
        }
        const uint32_t cA = sA[c % 3], cB = sB[c % 3];
        #pragma unroll
        for (int ks = 0; ks < 4; ks++) {
            uint32_t a[4][4];
            #pragma unroll
            for (int mi = 0; mi < 4; mi++) {
                int row = aRow + mi * 16;
                uint32_t addr = cA + row * 128 +
                    (((uint32_t)(ks * 32 + aH * 16)) ^ ((row & 7) << 4));
                LDSM_X4(a[mi][0], a[mi][1], a[mi][2], a[mi][3], addr);
            }
            uint32_t bf[4][2];
            #pragma unroll
            for (int bi = 0; bi < 2; bi++) {
                int row = wn * 32 + bi * 16 + bRowL;
                uint32_t addr = cB + row * 128 +
                    (((uint32_t)(ks * 32 + bH * 16)) ^ ((row & 7) << 4));
                LDSM_X4(bf[bi*2][0], bf[bi*2][1], bf[bi*2+1][0], bf[bi*2+1][1], addr);
            }
            #pragma unroll
            for (int mi = 0; mi < 4; mi++)
                #pragma unroll
                for (int ni = 0; ni < 4; ni++)
                    MMA16816(acc[mi][ni][0], acc[mi][ni][1], acc[mi][ni][2], acc[mi][ni][3],
                             a[mi][0], a[mi][1], a[mi][2], a[mi][3],
                             bf[ni][0], bf[ni][1]);
        }
    }
}

// ---------------- bf16 warp-MMA split GEMM: C[M,N] = A[M,KK] . B[N,KK]^T ----------------
template<int GELU>
__global__ __launch_bounds__(256, 2) void mma_gemm_kernel(
    const __nv_bfloat16* __restrict__ A,
    const __nv_bfloat16* __restrict__ B,
    const float* __restrict__ bias,
    float* __restrict__ C,
    int KK, int Ncols)
{
    extern __shared__ char dsm[];
    uint32_t base = (smem_to_u32(dsm) + 1023) & ~1023u;
    const uint32_t sA[3] = { base, base + 16384, base + 32768 };
    const uint32_t sB[3] = { base + 49152, base + 65536, base + 81920 };

    const int tid  = threadIdx.x;
    const int wid  = tid >> 5;
    const int lane = tid & 31;
    const int wm   = wid >> 2;
    const int wn   = wid & 3;
    const int m0 = blockIdx.y * 128;
    const int n0 = blockIdx.x * 128;
    const int aRow  = wm * 64 + (lane & 15);
    const int aH    = (lane >> 4) & 1;
    const int bRowL = (lane & 7) + ((lane >> 4) << 3);
    const int bH    = (lane >> 3) & 1;

    float acc[4][4][4];
    #pragma unroll
    for (int mi = 0; mi < 4; mi++)
        #pragma unroll
        for (int ni = 0; ni < 4; ni++)
            #pragma unroll
            for (int q = 0; q < 4; q++) acc[mi][ni][q] = 0.f;

    const __nv_bfloat16* Ab = A + (size_t)m0 * KK;
    const __nv_bfloat16* Bb = B + (size_t)n0 * KK;
    mma_mainloop(Ab, Bb, KK, KK >> 6, sA, sB, tid, aRow, aH, bRowL, bH, wn, acc);

    // epilogue: frag m16n8: {c0,c1} row lane/4, cols 2*(lane%4); {c2,c3} row+8
    #pragma unroll
    for (int ni = 0; ni < 4; ni++) {
        int col = n0 + wn * 32 + ni * 8 + (lane & 3) * 2;
        float b0 = bias[col], b1 = bias[col + 1];
        #pragma unroll
        for (int mi = 0; mi < 4; mi++) {
            int row = m0 + wm * 64 + mi * 16 + (lane >> 2);
            float2 v0, v1;
            v0.x = acc[mi][ni][0] + b0; v0.y = acc[mi][ni][1] + b1;
            v1.x = acc[mi][ni][2] + b0; v1.y = acc[mi][ni][3] + b1;
            if (GELU) {
                v0.x = gelu_exact(v0.x); v0.y = gelu_exact(v0.y);
                v1.x = gelu_exact(v1.x); v1.y = gelu_exact(v1.y);
            }
            *(float2*)(C + (size_t)row * Ncols + col)       = v0;
            *(float2*)(C + (size_t)(row + 8) * Ncols + col) = v1;
        }
    }
}

// ---------------- MMD via tensor-core Gram matrix ----------------
// gram g = X . Y^T (split bf16, KK=192, NC=3); e = exp((2g - |x|^2 - |y|^2)/4096); sum.
__global__ __launch_bounds__(256, 2) void mmd_mma_kernel(
    const __nv_bfloat16* __restrict__ A,   // X A-split [4096, 192]
    const __nv_bfloat16* __restrict__ B,   // Y B-split [4096, 192]
    const float* __restrict__ nX,
    const float* __restrict__ nY,
    double* __restrict__ accslot)
{
    extern __shared__ char dsm[];
    uint32_t base = (smem_to_u32(dsm) + 1023) & ~1023u;
    const uint32_t sA[3] = { base, base + 16384, base + 32768 };
    const uint32_t sB[3] = { base + 49152, base + 65536, base + 81920 };

    const int tid  = threadIdx.x;
    const int wid  = tid >> 5;
    const int lane = tid & 31;
    const int wm   = wid >> 2;
    const int wn   = wid & 3;
    const int m0 = blockIdx.y * 128;
    const int n0 = blockIdx.x * 128;
    const int aRow  = wm * 64 + (lane & 15);
    const int aH    = (lane >> 4) & 1;
    const int bRowL = (lane & 7) + ((lane >> 4) << 3);
    const int bH    = (lane >> 3) & 1;

    float acc[4][4][4];
    #pragma unroll
    for (int mi = 0; mi < 4; mi++)
        #pragma unroll
        for (int ni = 0; ni < 4; ni++)
            #pragma unroll
            for (int q = 0; q < 4; q++) acc[mi][ni][q] = 0.f;

    const int KK = 3 * DLAT;               // 192
    const __nv_bfloat16* Ab = A + (size_t)m0 * KK;
    const __nv_bfloat16* Bb = B + (size_t)n0 * KK;
    mma_mainloop(Ab, Bb, KK, 3, sA, sB, tid, aRow, aH, bRowL, bH, wn, acc);

    float total = 0.f;
    #pragma unroll
    for (int ni = 0; ni < 4; ni++) {
        int col = n0 + wn * 32 + ni * 8 + (lane & 3) * 2;
        float y0 = nY[col], y1 = nY[col + 1];
        #pragma unroll
        for (int mi = 0; mi < 4; mi++) {
            int row = m0 + wm * 64 + mi * 16 + (lane >> 2);
            float x0 = nX[row], x1 = nX[row + 8];
            total += __expf((2.f * acc[mi][ni][0] - x0 - y0) * (1.f/4096.f));
            total += __expf((2.f * acc[mi][ni][1] - x0 - y1) * (1.f/4096.f));
            total += __expf((2.f * acc[mi][ni][2] - x1 - y0) * (1.f/4096.f));
            total += __expf((2.f * acc[mi][ni][3] - x1 - y1) * (1.f/4096.f));
        }
    }
    #pragma unroll
    for (int o = 16; o; o >>= 1) total += __shfl_xor_sync(0xffffffffu, total, o);
    __shared__ float ws[8];
    if (lane == 0) ws[wid] = total;
    __syncthreads();
    if (tid == 0) {
        float bs = 0.f;
        #pragma unroll
        for (int w = 0; w < 8; w++) bs += ws[w];
        atomicAdd(accslot, (double)bs);
    }
}

// MMD prep: X[4096,64] fp32 -> A-split (hi|lo|hi), B-split (hi|hi|lo), row norms
__global__ __launch_bounds__(64) void mmd_prep_kernel(
    const float* __restrict__ X,
    __nv_bfloat16* __restrict__ As, __nv_bfloat16* __restrict__ Bs,
    float* __restrict__ nrm)
{
    const int r = blockIdx.x, t = threadIdx.x;  // 64 threads
    float v = X[(size_t)r * DLAT + t];
    __nv_bfloat16 hi = __float2bfloat16(v);
    __nv_bfloat16 lo = __float2bfloat16(v - __bfloat162float(hi));
    size_t b = (size_t)r * 3 * DLAT;
    As[b + t] = hi; As[b + DLAT + t] = lo; As[b + 2*DLAT + t] = hi;
    Bs[b + t] = hi; Bs[b + DLAT + t] = hi; Bs[b + 2*DLAT + t] = lo;

    float s = v * v;
    #pragma unroll
    for (int o = 16; o; o >>= 1) s += __shfl_xor_sync(0xffffffffu, s, o);
    __shared__ float w2[2];
    if ((t & 31) == 0) w2[t >> 5] = s;
    __syncthreads();
    if (t == 0) nrm[r] = w2[0] + w2[1];
}

// ---------------- conversion kernels ----------------
__global__ void split_act_kernel(const float* __restrict__ x, __nv_bfloat16* __restrict__ o, int Kseg) {
    int r = blockIdx.y;
    int c = blockIdx.x * 256 + threadIdx.x;
    float v = x[(size_t)r * Kseg + c];
    __nv_bfloat16 hi = __float2bfloat16(v);
    __nv_bfloat16 lo = __float2bfloat16(v - __bfloat162float(hi));
    size_t b = (size_t)r * 3 * Kseg;
    o[b + c] = hi;
    o[b + Kseg + c] = lo;
    o[b + 2 * Kseg + c] = hi;
}

__global__ void wsplit_kernel(const float* __restrict__ W, __nv_bfloat16* __restrict__ o, int K, int N) {
    __shared__ float t[32][33];
    int n0 = blockIdx.x * 32, k0 = blockIdx.y * 32;
    int tx = threadIdx.x, ty = threadIdx.y;   // 32 x 8
    #pragma unroll
    for (int i = 0; i < 4; i++)
        t[ty + i * 8][tx] = W[(size_t)(k0 + ty + i * 8) * N + n0 + tx];
    __syncthreads();
    #pragma unroll
    for (int i = 0; i < 4; i++) {
        int n = n0 + ty + i * 8;
        float v = t[tx][ty + i * 8];
        __nv_bfloat16 hi = __float2bfloat16(v);
        __nv_bfloat16 lo = __float2bfloat16(v - __bfloat162float(hi));
        size_t b = (size_t)n * 3 * K;
        o[b + k0 + tx] = hi;
        o[b + K + k0 + tx] = hi;
        o[b + 2 * K + k0 + tx] = lo;
    }
}

// ---------------- decoder GEMM1 (K=64) fp32 FMA, GELU, split-bf16 output ----------------
__global__ __launch_bounds__(256) void sgemm_split_kernel(
    const float* __restrict__ A,   // [M,K]
    const float* __restrict__ B,   // [K,N]
    const float* __restrict__ bias,
    __nv_bfloat16* __restrict__ Cs,// [M, 3*Kout] hi|lo|hi
    int M, int N, int K, int Kout)
{
    __shared__ float As[8][128];
    __shared__ float Bs[8][128];
    const int tid = threadIdx.x;
    const int tx = tid & 15;
    const int ty = tid >> 4;
    const int bx = blockIdx.x, by = blockIdx.y;

    const float* Abp = A + (size_t)by * 128 * K;
    const float* Bbp = B + (size_t)bx * 128;

    const int arow = tid >> 1;
    const int acol = (tid & 1) * 4;
    const int brow = tid >> 5;
    const int bcol = (tid & 31) * 4;

    float acc[8][8];
    #pragma unroll
    for (int i = 0; i < 8; i++)
        #pragma unroll
        for (int j = 0; j < 8; j++) acc[i][j] = 0.f;

    for (int k0 = 0; k0 < K; k0 += 8) {
        float4 av = *(const float4*)(Abp + (size_t)arow * K + k0 + acol);
        As[acol+0][arow] = av.x; As[acol+1][arow] = av.y;
        As[acol+2][arow] = av.z; As[acol+3][arow] = av.w;
        *(float4*)&Bs[brow][bcol] = *(const float4*)(Bbp + (size_t)(k0 + brow) * N + bcol);
        __syncthreads();
        #pragma unroll
        for (int k = 0; k < 8; k++) {
            float4 a0 = *(const float4*)&As[k][ty * 4];
            float4 a1 = *(const float4*)&As[k][64 + ty * 4];
            float4 b0 = *(const float4*)&Bs[k][tx * 4];
            float4 b1 = *(const float4*)&Bs[k][64 + tx * 4];
            float a[8] = {a0.x,a0.y,a0.z,a0.w,a1.x,a1.y,a1.z,a1.w};
            float b[8] = {b0.x,b0.y,b0.z,b0.w,b1.x,b1.y,b1.z,b1.w};
            #pragma unroll
            for (int i = 0; i < 8; i++)
                #pragma unroll
                for (int j = 0; j < 8; j++)
                    acc[i][j] = fmaf(a[i], b[j], acc[i][j]);
        }
        __syncthreads();
    }

    #pragma unroll
    for (int ih = 0; ih < 2; ih++)
      #pragma unroll
      for (int i = 0; i < 4; i++) {
        int row = by * 128 + ih * 64 + ty * 4 + i;
        size_t rb = (size_t)row * 3 * Kout;
        #pragma unroll
        for (int jh = 0; jh < 2; jh++) {
            int col0 = bx * 128 + jh * 64 + tx * 4;
            __nv_bfloat16 hv[4], lv[4];
            #pragma unroll
            for (int j = 0; j < 4; j++) {
                float t = gelu_exact(acc[ih*4 + i][jh*4 + j] + bias[col0 + j]);
                hv[j] = __float2bfloat16(t);
                lv[j] = __float2bfloat16(t - __bfloat162float(hv[j]));
            }
            *(uint2*)(Cs + rb + col0)            = *(uint2*)hv;
            *(uint2*)(Cs + rb + Kout + col0)     = *(uint2*)lv;
            *(uint2*)(Cs + rb + 2 * Kout + col0) = *(uint2*)hv;
        }
      }
}

// ---------------- encoder GEMM2 (N=64) fused with LayerNorm over 64 ----------------
__global__ __launch_bounds__(256) void enc2_ln_kernel(
    const float* __restrict__ A,   // [4096, 4096]
    const float* __restrict__ B,   // [4096, 64]
    const float* __restrict__ bias,
    const float* __restrict__ lg, const float* __restrict__ lb,
    float* __restrict__ out)       // [4096, 64]
{
    __shared__ float As[32][33];
    __shared__ float Bs[32][64];
    __shared__ float P[32][65];
    __shared__ float smu[32], srs[32];
    const int tid = threadIdx.x;
    const int tx = tid & 63;
    const int ty = tid >> 6;
    const int row0 = blockIdx.x * 32;
    const int ar = tid >> 3;
    const int ac = (tid & 7) * 4;

    float acc[8] = {0.f,0.f,0.f,0.f,0.f,0.f,0.f,0.f};

    for (int k0 = 0; k0 < DI; k0 += 32) {
        float4 av = *(const float4*)(A + (size_t)(row0 + ar) * DI + k0 + ac);
        As[ar][ac+0] = av.x; As[ar][ac+1] = av.y;
        As[ar][ac+2] = av.z; As[ar][ac+3] = av.w;
        #pragma unroll
        for (int l = 0; l < 2; l++) {
            int idx = tid + l * 256;
            int br = idx >> 4, bc = (idx & 15) * 4;
            *(float4*)&Bs[br][bc] = *(const float4*)(B + (size_t)(k0 + br) * DLAT + bc);
        }
        __syncthreads();
        #pragma unroll
        for (int k = 0; k < 32; k++) {
            float bv = Bs[k][tx];
            #pragma unroll
            for (int i = 0; i < 8; i++)
                acc[i] = fmaf(As[ty*8 + i][k], bv, acc[i]);
        }
        __syncthreads();
    }

    #pragma unroll
    for (int i = 0; i < 8; i++)
        P[ty*8 + i][tx] = acc[i] + bias[tx];
    __syncthreads();

    if (tid < 32) {
        float s = 0.f;
        for (int c = 0; c < 64; c++) s += P[tid][c];
        float mu = s * (1.f/64.f);
        float vs = 0.f;
        for (int c = 0; c < 64; c++) { float d = P[tid][c] - mu; vs += d*d; }
        smu[tid] = mu;
        srs[tid] = rsqrtf(vs * (1.f/64.f) + 1e-9f);
    }
    __syncthreads();

    #pragma unroll
    for (int i = 0; i < 8; i++) {
        int r = ty*8 + i;
        out[(size_t)(row0 + r) * DLAT + tx] =
            (P[r][tx] - smu[r]) * srs[r] * lg[tx] + lb[tx];
    }
}

// ---------------- in-place LayerNorm over 1024 ----------------
__global__ __launch_bounds__(256) void ln_inplace_kernel(
    float* __restrict__ x, const float* __restrict__ g, const float* __restrict__ b)
{
    const int row = blockIdx.x;
    float* p = x + (size_t)row * D0;
    const int tid = threadIdx.x;
    __shared__ float red[8];

    float v[4];
    float s = 0.f;
    #pragma unroll
    for (int i = 0; i < 4; i++) { v[i] = p[tid + i*256]; s += v[i]; }
    #pragma unroll
    for (int o = 16; o; o >>= 1) s += __shfl_xor_sync(0xffffffffu, s, o);
    if ((tid & 31) == 0) red[tid >> 5] = s;
    __syncthreads();
    float mu = 0.f;
    #pragma unroll
    for (int w = 0; w < 8; w++) mu += red[w];
    mu *= (1.f/1024.f);
    __syncthreads();

    float ss = 0.f;
    #pragma unroll
    for (int i = 0; i < 4; i++) { float d = v[i] - mu; ss += d*d; }
    #pragma unroll
    for (int o = 16; o; o >>= 1) ss += __shfl_xor_sync(0xffffffffu, ss, o);
    if ((tid & 31) == 0) red[tid >> 5] = ss;
    __syncthreads();
    float var = 0.f;
    #pragma unroll
    for (int w = 0; w < 8; w++) var += red[w];
    var *= (1.f/1024.f);
    float rs = rsqrtf(var + 1e-9f);

    #pragma unroll
    for (int i = 0; i < 4; i++) {
        int c = tid + i*256;
        p[c] = (v[i] - mu) * rs * g[c] + b[c];
    }
}

__global__ void zero_acc_kernel() {
    if (threadIdx.x < 3) g_acc[threadIdx.x] = 0.0;
}

__global__ void finalize_kernel(float* __restrict__ loss_out) {
    const double inv = 1.0 / ((double)NTOK * (double)NTOK);
    double mmd = (g_acc[0] + g_acc[1] - 2.0 * g_acc[2]) * inv;
    *loss_out = (float)(mmd * 64.0);
}

extern "C" void kernel_launch(void* const* d_in, const int* in_sizes, int n_in,
                              void* d_out, int out_size)
{
    const float* hidden  = (const float*)d_in[0];
    const float* true_s  = (const float*)d_in[1];
    const float* enc_w1  = (const float*)d_in[2];
    const float* enc_b1  = (const float*)d_in[3];
    const float* enc_w2  = (const float*)d_in[4];
    const float* enc_b2  = (const float*)d_in[5];
    const float* enc_lg  = (const float*)d_in[6];
    const float* enc_lb  = (const float*)d_in[7];
    const float* dec_w1  = (const float*)d_in[8];
    const float* dec_b1  = (const float*)d_in[9];
    const float* dec_w2  = (const float*)d_in[10];
    const float* dec_b2  = (const float*)d_in[11];
    const float* dec_lg  = (const float*)d_in[12];
    const float* dec_lb  = (const float*)d_in[13];

    float* recon  = (float*)d_out;                          // [4096, 1024]
    float* latent = recon + (size_t)NTOK * D0;              // [4096, 64]
    float* loss   = latent + (size_t)NTOK * DLAT;           // [1]

    float*         h1;  cudaGetSymbolAddress((void**)&h1,  g_h1);
    __nv_bfloat16* as;  cudaGetSymbolAddress((void**)&as,  g_as);
    __nv_bfloat16* w1s; cudaGetSymbolAddress((void**)&w1s, g_w1s);
    __nv_bfloat16* h1s; cudaGetSymbolAddress((void**)&h1s, g_h1s);
    __nv_bfloat16* w2s; cudaGetSymbolAddress((void**)&w2s, g_w2s);
    __nv_bfloat16 *tsA, *tsB, *laA, *laB;
    cudaGetSymbolAddress((void**)&tsA, g_tsA);
    cudaGetSymbolAddress((void**)&tsB, g_tsB);
    cudaGetSymbolAddress((void**)&laA, g_laA);
    cudaGetSymbolAddress((void**)&laB, g_laB);
    float *tn, *ln;
    cudaGetSymbolAddress((void**)&tn, g_tn);
    cudaGetSymbolAddress((void**)&ln, g_ln);
    double*        acc; cudaGetSymbolAddress((void**)&acc, g_acc);

    const int TC_SMEM = 99328;   // 1KB align pad + 3 stages x (16KB A + 16KB B)
    (void)cudaFuncSetAttribute(mma_gemm_kernel<1>, cudaFuncAttributeMaxDynamicSharedMemorySize, TC_SMEM);
    (void)cudaFuncSetAttribute(mma_gemm_kernel<0>, cudaFuncAttributeMaxDynamicSharedMemorySize, TC_SMEM);
    (void)cudaFuncSetAttribute(mmd_mma_kernel,     cudaFuncAttributeMaxDynamicSharedMemorySize, TC_SMEM);

    zero_acc_kernel<<<1, 32>>>();

    // --- splits for encoder GEMM1 ---
    split_act_kernel<<<dim3(D0/256, NTOK), 256>>>(hidden, as, D0);
    wsplit_kernel<<<dim3(DI/32, D0/32), dim3(32, 8)>>>(enc_w1, w1s, D0, DI);

    // encoder GEMM1 (HMMA bf16-split, GELU) -> h1 fp32 [4096, 4096]
    mma_gemm_kernel<1><<<dim3(DI/128, NTOK/128), 256, TC_SMEM>>>(as, w1s, enc_b1, h1,
                                                                 3 * D0, DI);

    // encoder GEMM2 + LN(64) -> latent fp32
    enc2_ln_kernel<<<NTOK/32, 256>>>(h1, enc_w2, enc_b2, enc_lg, enc_lb, latent);

    // MMD preps (splits + norms)
    mmd_prep_kernel<<<NTOK, 64>>>(true_s, tsA, tsB, tn);
    mmd_prep_kernel<<<NTOK, 64>>>(latent, laA, laB, ln);

    // MMD terms via tensor-core Gram
    mmd_mma_kernel<<<dim3(NTOK/128, NTOK/128), 256, TC_SMEM>>>(tsA, tsB, tn, tn, acc + 0);
    mmd_mma_kernel<<<dim3(NTOK/128, NTOK/128), 256, TC_SMEM>>>(laA, laB, ln, ln, acc + 1);
    mmd_mma_kernel<<<dim3(NTOK/128, NTOK/128), 256, TC_SMEM>>>(tsA, laB, tn, ln, acc + 2);

    // decoder GEMM1 (fp32 FMA, K=64) + GELU -> split bf16 h1s [4096, 12288]
    sgemm_split_kernel<<<dim3(DI/128, NTOK/128), 256>>>(latent, dec_w1, dec_b1, h1s,
                                                        NTOK, DI, DLAT, DI);

    // decoder weight split
    wsplit_kernel<<<dim3(D0/32, DI/32), dim3(32, 8)>>>(dec_w2, w2s, DI, D0);

    // decoder GEMM2 (HMMA bf16-split, bias only) -> recon fp32 [4096, 1024]
    mma_gemm_kernel<0><<<dim3(D0/128, NTOK/128), 256, TC_SMEM>>>(h1s, w2s, dec_b2, recon,
                                                                 3 * DI, D0);

    // LN(1024) in place
    ln_inplace_kernel<<<NTOK, 256>>>(recon, dec_lg, dec_lb);

    finalize_kernel<<<1, 1>>>(loss);
}

// round 15
// speedup vs baseline: 2.6997x; 1.1812x over previous
#include <cuda_runtime.h>
#include <cuda_bf16.h>
#include <math.h>
#include <stdint.h>

#define NTOK 4096
#define D0   1024
#define DI   4096
#define DLAT 64
#define KSLICES 8

// ---------------- device scratch (no allocs allowed) ----------------
__device__ __nv_bfloat16 g_as [(size_t)NTOK * 3 * D0];      // hidden split  [4096, 3072]  hi|lo|hi
__device__ __nv_bfloat16 g_w1s[(size_t)DI   * 3 * D0];      // enc_w1^T split [4096, 3072] hi|hi|lo
__device__ __nv_bfloat16 g_h1s[(size_t)NTOK * 3 * DI];      // hidden split [4096,12288] hi|lo|hi (enc then dec)
__device__ __nv_bfloat16 g_w2e[(size_t)DLAT * 3 * DI];      // enc_w2^T split [64, 12288] hi|hi|lo
__device__ __nv_bfloat16 g_w1d[(size_t)DI   * 3 * DLAT];    // dec_w1^T split [4096, 192] hi|hi|lo
__device__ __nv_bfloat16 g_w2s[(size_t)D0   * 3 * DI];      // dec_w2^T split [1024,12288] hi|hi|lo
__device__ float         g_p  [(size_t)KSLICES * NTOK * DLAT]; // enc2 split-K partials
// MMD splits: [4096, 192] A-form (hi|lo|hi) and B-form (hi|hi|lo) + fp32 row norms
__device__ __nv_bfloat16 g_tsA[(size_t)NTOK * 3 * DLAT];
__device__ __nv_bfloat16 g_tsB[(size_t)NTOK * 3 * DLAT];
__device__ __nv_bfloat16 g_laA[(size_t)NTOK * 3 * DLAT];
__device__ __nv_bfloat16 g_laB[(size_t)NTOK * 3 * DLAT];
__device__ float         g_tn [NTOK];
__device__ float         g_ln [NTOK];
__device__ double        g_acc[3];

__device__ __forceinline__ float gelu_exact(float x) {
    return 0.5f * x * (1.0f + erff(x * 0.70710678118654752f));
}

__device__ __forceinline__ uint32_t smem_to_u32(const void* p) {
    uint32_t a;
    asm("{ .reg .u64 t; cvta.to.shared.u64 t, %1; cvt.u32.u64 %0, t; }" : "=r"(a) : "l"(p));
    return a;
}

#define CP_COMMIT() asm volatile("cp.async.commit_group;" ::: "memory")
#define CP_WAIT(n)  asm volatile("cp.async.wait_group %0;" :: "n"(n) : "memory")

// load one 128x64(bf16) K-major swizzled tile for A and B via cp.async (16B units), 256 thr
__device__ __forceinline__ void load_chunk256(const __nv_bfloat16* __restrict__ Ab,
                                              const __nv_bfloat16* __restrict__ Bb,
                                              int KK, int k0, uint32_t sA, uint32_t sB, int tid) {
    #pragma unroll
    for (int i = 0; i < 4; i++) {
        int unit = tid + (i << 8);      // 0..1023
        int r    = unit >> 3;           // 0..127
        int c16  = unit & 7;            // 0..7 (16B blocks)
        uint32_t off = (uint32_t)(r * 128 + ((c16 * 16) ^ ((r & 7) << 4)));
        const void* srcA = (const void*)(Ab + (size_t)r * KK + k0 + c16 * 8);
        const void* srcB = (const void*)(Bb + (size_t)r * KK + k0 + c16 * 8);
        asm volatile("cp.async.cg.shared.global [%0], [%1], 16;" :: "r"(sA + off), "l"(srcA));
        asm volatile("cp.async.cg.shared.global [%0], [%1], 16;" :: "r"(sB + off), "l"(srcB));
    }
}

#define LDSM_X4(r0,r1,r2,r3,addr) \
    asm volatile("ldmatrix.sync.aligned.m8n8.x4.shared.b16 {%0,%1,%2,%3}, [%4];" \
        : "=r"(r0), "=r"(r1), "=r"(r2), "=r"(r3) : "r"(addr))

#define MMA16816(c0,c1,c2,c3,a0,a1,a2,a3,b0,b1) \
    asm volatile("mma.sync.aligned.m16n8k16.row.col.f32.bf16.bf16.f32 " \
        "{%0,%1,%2,%3}, {%4,%5,%6,%7}, {%8,%9}, {%0,%1,%2,%3};" \
        : "+f"(c0), "+f"(c1), "+f"(c2), "+f"(c3) \
        : "r"(a0), "r"(a1), "r"(a2), "r"(a3), "r"(b0), "r"(b1))

// Shared mainloop: 128x128 tile, 8 warps (2x4), warp tile 64x32, 3-stage cp.async
// pipeline, single __syncthreads per chunk. 96KB smem (3 x (16KB A + 16KB B)).
__device__ __forceinline__ void mma_mainloop(
    const __nv_bfloat16* __restrict__ Ab, const __nv_bfloat16* __restrict__ Bb,
    int KK, int NC, const uint32_t* sA, const uint32_t* sB,
    int tid, int aRow, int aH, int bRowL, int bH, int wn,
    float acc[4][4][4])
{
    load_chunk256(Ab, Bb, KK, 0, sA[0], sB[0], tid);
    CP_COMMIT();
    if (NC > 1) {
        load_chunk256(Ab, Bb, KK, 64, sA[1], sB[1], tid);
        CP_COMMIT();
    }

    for (int c = 0; c < NC; c++) {
        if (c + 1 < NC) { CP_WAIT(1); } else { CP_WAIT(0); }
        __syncthreads();
        if (c + 2 < NC) {
            int s = (c + 2) % 3;
            load_chunk256(Ab, Bb, KK, (c + 2) << 6, sA[s], sB[s], tid);
            CP_COMMIT();
        }
        const uint32_t cA = sA[c % 3], cB = sB[c % 3];
        #pragma unroll
        for (int ks = 0; ks < 4; ks++) {
            uint32_t a[4][4];
            #pragma unroll
            for (int mi = 0; mi < 4; mi++) {
                int row = aRow + mi * 16;
                uint32_t addr = cA + row * 128 +
                    (((uint32_t)(ks * 32 + aH * 16)) ^ ((row & 7) << 4));
                LDSM_X4(a[mi][0], a[mi][1], a[mi][2], a[mi][3], addr);
            }
            uint32_t bf[4][2];
            #pragma unroll
            for (int bi = 0; bi < 2; bi++) {
                int row = wn * 32 + bi * 16 + bRowL;
                uint32_t addr = cB + row * 128 +
                    (((uint32_t)(ks * 32 + bH * 16)) ^ ((row & 7) << 4));
                LDSM_X4(bf[bi*2][0], bf[bi*2][1], bf[bi*2+1][0], bf[bi*2+1][1], addr);
            }
            #pragma unroll
            for (int mi = 0; mi < 4; mi++)
                #pragma unroll
                for (int ni = 0; ni < 4; ni++)
                    MMA16816(acc[mi][ni][0], acc[mi][ni][1], acc[mi][ni][2], acc[mi][ni][3],
                             a[mi][0], a[mi][1], a[mi][2], a[mi][3],
                             bf[ni][0], bf[ni][1]);
        }
    }
}

// write split pair (hi|lo|hi) for two adjacent columns
__device__ __forceinline__ void write_split2(__nv_bfloat16* p, int Kout, float x0, float x1) {
    __nv_bfloat16 h0 = __float2bfloat16(x0);
    __nv_bfloat16 h1 = __float2bfloat16(x1);
    __nv_bfloat16 l0 = __float2bfloat16(x0 - __bfloat162float(h0));
    __nv_bfloat16 l1 = __float2bfloat16(x1 - __bfloat162float(h1));
    __nv_bfloat162 hv; hv.x = h0; hv.y = h1;
    __nv_bfloat162 lv; lv.x = l0; lv.y = l1;
    *(__nv_bfloat162*)(p)            = hv;
    *(__nv_bfloat162*)(p + Kout)     = lv;
    *(__nv_bfloat162*)(p + 2 * Kout) = hv;
}

// ---------------- bf16 warp-MMA split GEMM: C[M,N] = A[M,KK] . B[N,KK]^T ----------------
// OUTMODE 0: fp32 out = acc + bias  (C = float*, Ncols)
// OUTMODE 2: split bf16 out = gelu(acc + bias) -> hi|lo|hi rows of width 3*Kout
template<int OUTMODE>
__global__ __launch_bounds__(256, 2) void mma_gemm_kernel(
    const __nv_bfloat16* __restrict__ A,
    const __nv_bfloat16* __restrict__ B,
    const float* __restrict__ bias,
    float* __restrict__ C,
    __nv_bfloat16* __restrict__ Cs,
    int KK, int Ncols, int Kout)
{
    extern __shared__ char dsm[];
    uint32_t base = (smem_to_u32(dsm) + 1023) & ~1023u;
    const uint32_t sA[3] = { base, base + 16384, base + 32768 };
    const uint32_t sB[3] = { base + 49152, base + 65536, base + 81920 };

    const int tid  = threadIdx.x;
    const int wid  = tid >> 5;
    const int lane = tid & 31;
    const int wm   = wid >> 2;
    const int wn   = wid & 3;
    const int m0 = blockIdx.y * 128;
    const int n0 = blockIdx.x * 128;
    const int aRow  = wm * 64 + (lane & 15);
    const int aH    = (lane >> 4) & 1;
    const int bRowL = (lane & 7) + ((lane >> 4) << 3);
    const int bH    = (lane >> 3) & 1;

    float acc[4][4][4];
    #pragma unroll
    for (int mi = 0; mi < 4; mi++)
        #pragma unroll
        for (int ni = 0; ni < 4; ni++)
            #pragma unroll
            for (int q = 0; q < 4; q++) acc[mi][ni][q] = 0.f;

    const __nv_bfloat16* Ab = A + (size_t)m0 * KK;
    const __nv_bfloat16* Bb = B + (size_t)n0 * KK;
    mma_mainloop(Ab, Bb, KK, KK >> 6, sA, sB, tid, aRow, aH, bRowL, bH, wn, acc);

    // epilogue: frag m16n8: {c0,c1} row lane/4, cols 2*(lane%4); {c2,c3} row+8
    #pragma unroll
    for (int ni = 0; ni < 4; ni++) {
        int col = n0 + wn * 32 + ni * 8 + (lane & 3) * 2;
        float b0 = bias[col], b1 = bias[col + 1];
        #pragma unroll
        for (int mi = 0; mi < 4; mi++) {
            int row = m0 + wm * 64 + mi * 16 + (lane >> 2);
            float t00 = acc[mi][ni][0] + b0, t01 = acc[mi][ni][1] + b1;
            float t10 = acc[mi][ni][2] + b0, t11 = acc[mi][ni][3] + b1;
            if (OUTMODE == 0) {
                float2 v0; v0.x = t00; v0.y = t01;
                float2 v1; v1.x = t10; v1.y = t11;
                *(float2*)(C + (size_t)row * Ncols + col)       = v0;
                *(float2*)(C + (size_t)(row + 8) * Ncols + col) = v1;
            } else {
                t00 = gelu_exact(t00); t01 = gelu_exact(t01);
                t10 = gelu_exact(t10); t11 = gelu_exact(t11);
                write_split2(Cs + (size_t)row * 3 * Kout + col, Kout, t00, t01);
                write_split2(Cs + (size_t)(row + 8) * 3 * Kout + col, Kout, t10, t11);
            }
        }
    }
}

// ---------------- encoder GEMM2 split-K partials: [128,64] tile, KK=12288 ----------------
// grid (KSLICES, NTOK/128). A = h1s [4096, 12288] hi|lo|hi. B = w2e [64, 12288] hi|hi|lo.
__global__ __launch_bounds__(256, 2) void enc2_partial_kernel(
    const __nv_bfloat16* __restrict__ A,
    const __nv_bfloat16* __restrict__ B,
    float* __restrict__ P)           // [KSLICES][4096][64]
{
    extern __shared__ char dsm[];
    uint32_t base = (smem_to_u32(dsm) + 1023) & ~1023u;
    const uint32_t sA[3] = { base, base + 16384, base + 32768 };
    const uint32_t sB[3] = { base + 49152, base + 57344, base + 65536 };

    const int tid  = threadIdx.x;
    const int wid  = tid >> 5;
    const int lane = tid & 31;
    const int wm   = wid >> 1;            // 0..3 (32-row strips)
    const int wn   = wid & 1;             // 0..1 (32-col halves)
    const int kslice = blockIdx.x;
    const int m0 = blockIdx.y * 128;
    const int KK = 3 * DI;                // 12288
    const int kbeg = kslice * (KK / KSLICES);   // 1536 per slice
    const int NC = (KK / KSLICES) >> 6;   // 24

    const int aRow  = wm * 32 + (lane & 15);
    const int aH    = (lane >> 4) & 1;
    const int bRowL = (lane & 7) + ((lane >> 4) << 3);
    const int bH    = (lane >> 3) & 1;

    float acc[2][4][4];
    #pragma unroll
    for (int mi = 0; mi < 2; mi++)
        #pragma unroll
        for (int ni = 0; ni < 4; ni++)
            #pragma unroll
            for (int q = 0; q < 4; q++) acc[mi][ni][q] = 0.f;

    const __nv_bfloat16* Ab = A + (size_t)m0 * KK + kbeg;
    const __nv_bfloat16* Bb = B + kbeg;

    // loader: A 128 rows (4 iters), B 64 rows (2 iters)
    auto load_c = [&](int k0, uint32_t dA, uint32_t dB) {
        #pragma unroll
        for (int i = 0; i < 4; i++) {
            int unit = tid + (i << 8);
            int r = unit >> 3, c16 = unit & 7;
            uint32_t off = (uint32_t)(r * 128 + ((c16 * 16) ^ ((r & 7) << 4)));
            const void* src = (const void*)(Ab + (size_t)r * KK + k0 + c16 * 8);
            asm volatile("cp.async.cg.shared.global [%0], [%1], 16;" :: "r"(dA + off), "l"(src));
        }
        #pragma unroll
        for (int i = 0; i < 2; i++) {
            int unit = tid + (i << 8);
            int r = unit >> 3, c16 = unit & 7;
            uint32_t off = (uint32_t)(r * 128 + ((c16 * 16) ^ ((r & 7) << 4)));
            const void* src = (const void*)(Bb + (size_t)r * KK + k0 + c16 * 8);
            asm volatile("cp.async.cg.shared.global [%0], [%1], 16;" :: "r"(dB + off), "l"(src));
        }
    };

    load_c(0, sA[0], sB[0]); CP_COMMIT();
    load_c(64, sA[1], sB[1]); CP_COMMIT();

    for (int c = 0; c < NC; c++) {
        if (c + 1 < NC) { CP_WAIT(1); } else { CP_WAIT(0); }
        __syncthreads();
        if (c + 2 < NC) {
            int s = (c + 2) % 3;
            load_c((c + 2) << 6, sA[s], sB[s]);
            CP_COMMIT();
        }
        const uint32_t cA = sA[c % 3], cB = sB[c % 3];
        #pragma unroll
        for (int ks = 0; ks < 4; ks++) {
            uint32_t a[2][4];
            #pragma unroll
            for (int mi = 0; mi < 2; mi++) {
                int row = aRow + mi * 16;
                uint32_t addr = cA + row * 128 +
                    (((uint32_t)(ks * 32 + aH * 16)) ^ ((row & 7) << 4));
                LDSM_X4(a[mi][0], a[mi][1], a[mi][2], a[mi][3], addr);
            }
            uint32_t bf[4][2];
            #pragma unroll
            for (int bi = 0; bi < 2; bi++) {
                int row = wn * 32 + bi * 16 + bRowL;
                uint32_t addr = cB + row * 128 +
                    (((uint32_t)(ks * 32 + bH * 16)) ^ ((row & 7) << 4));
                LDSM_X4(bf[bi*2][0], bf[bi*2][1], bf[bi*2+1][0], bf[bi*2+1][1], addr);
            }
            #pragma unroll
            for (int mi = 0; mi < 2; mi++)
                #pragma unroll
                for (int ni = 0; ni < 4; ni++)
                    MMA16816(acc[mi][ni][0], acc[mi][ni][1], acc[mi][ni][2], acc[mi][ni][3],
                             a[mi][0], a[mi][1], a[mi][2], a[mi][3],
                             bf[ni][0], bf[ni][1]);
        }
    }

    float* Pb = P + (size_t)kslice * NTOK * DLAT;
    #pragma unroll
    for (int ni = 0; ni < 4; ni++) {
        int col = wn * 32 + ni * 8 + (lane & 3) * 2;
        #pragma unroll
        for (int mi = 0; mi < 2; mi++) {
            int row = m0 + wm * 32 + mi * 16 + (lane >> 2);
            float2 v0; v0.x = acc[mi][ni][0]; v0.y = acc[mi][ni][1];
            float2 v1; v1.x = acc[mi][ni][2]; v1.y = acc[mi][ni][3];
            *(float2*)(Pb + (size_t)row * DLAT + col)       = v0;
            *(float2*)(Pb + (size_t)(row + 8) * DLAT + col) = v1;
        }
    }
}

// reduce KSLICES partials + bias + LayerNorm(64) -> latent
__global__ __launch_bounds__(64) void enc2_reduce_ln_kernel(
    const float* __restrict__ P, const float* __restrict__ bias,
    const float* __restrict__ lg, const float* __restrict__ lb,
    float* __restrict__ out)
{
    const int r = blockIdx.x, t = threadIdx.x;
    float v = bias[t];
    #pragma unroll
    for (int s = 0; s < KSLICES; s++)
        v += P[((size_t)s * NTOK + r) * DLAT + t];

    __shared__ float w2[2];
    float s1 = v;
    #pragma unroll
    for (int o = 16; o; o >>= 1) s1 += __shfl_xor_sync(0xffffffffu, s1, o);
    if ((t & 31) == 0) w2[t >> 5] = s1;
    __syncthreads();
    float mu = (w2[0] + w2[1]) * (1.f/64.f);
    __syncthreads();

    float d = v - mu;
    float s2 = d * d;
    #pragma unroll
    for (int o = 16; o; o >>= 1) s2 += __shfl_xor_sync(0xffffffffu, s2, o);
    if ((t & 31) == 0) w2[t >> 5] = s2;
    __syncthreads();
    float rs = rsqrtf((w2[0] + w2[1]) * (1.f/64.f) + 1e-9f);

    out[(size_t)r * DLAT + t] = d * rs * lg[t] + lb[t];
}

// ---------------- MMD via tensor-core Gram matrix ----------------
__global__ __launch_bounds__(256, 2) void mmd_mma_kernel(
    const __nv_bfloat16* __restrict__ A,   // X A-split [4096, 192]
    const __nv_bfloat16* __restrict__ B,   // Y B-split [4096, 192]
    const float* __restrict__ nX,
    const float* __restrict__ nY,
    double* __restrict__ accslot)
{
    extern __shared__ char dsm[];
    uint32_t base = (smem_to_u32(dsm) + 1023) & ~1023u;
    const uint32_t sA[3] = { base, base + 16384, base + 32768 };
    const uint32_t sB[3] = { base + 49152, base + 65536, base + 81920 };

    const int tid  = threadIdx.x;
    const int wid  = tid >> 5;
    const int lane = tid & 31;
    const int wm   = wid >> 2;
    const int wn   = wid & 3;
    const int m0 = blockIdx.y * 128;
    const int n0 = blockIdx.x * 128;
    const int aRow  = wm * 64 + (lane & 15);
    const int aH    = (lane >> 4) & 1;
    const int bRowL = (lane & 7) + ((lane >> 4) << 3);
    const int bH    = (lane >> 3) & 1;

    float acc[4][4][4];
    #pragma unroll
    for (int mi = 0; mi < 4; mi++)
        #pragma unroll
        for (int ni = 0; ni < 4; ni++)
            #pragma unroll
            for (int q = 0; q < 4; q++) acc[mi][ni][q] = 0.f;

    const int KK = 3 * DLAT;               // 192
    const __nv_bfloat16* Ab = A + (size_t)m0 * KK;
    const __nv_bfloat16* Bb = B + (size_t)n0 * KK;
    mma_mainloop(Ab, Bb, KK, 3, sA, sB, tid, aRow, aH, bRowL, bH, wn, acc);

    float total = 0.f;
    #pragma unroll
    for (int ni = 0; ni < 4; ni++) {
        int col = n0 + wn * 32 + ni * 8 + (lane & 3) * 2;
        float y0 = nY[col], y1 = nY[col + 1];
        #pragma unroll
        for (int mi = 0; mi < 4; mi++) {
            int row = m0 + wm * 64 + mi * 16 + (lane >> 2);
            float x0 = nX[row], x1 = nX[row + 8];
            total += __expf((2.f * acc[mi][ni][0] - x0 - y0) * (1.f/4096.f));
            total += __expf((2.f * acc[mi][ni][1] - x0 - y1) * (1.f/4096.f));
            total += __expf((2.f * acc[mi][ni][2] - x1 - y0) * (1.f/4096.f));
            total += __expf((2.f * acc[mi][ni][3] - x1 - y1) * (1.f/4096.f));
        }
    }
    #pragma unroll
    for (int o = 16; o; o >>= 1) total += __shfl_xor_sync(0xffffffffu, total, o);
    __shared__ float ws[8];
    if (lane == 0) ws[wid] = total;
    __syncthreads();
    if (tid == 0) {
        float bs = 0.f;
        #pragma unroll
        for (int w = 0; w < 8; w++) bs += ws[w];
        atomicAdd(accslot, (double)bs);
    }
}

// MMD prep: X[4096,64] fp32 -> A-split (hi|lo|hi), B-split (hi|hi|lo), row norms
__global__ __launch_bounds__(64) void mmd_prep_kernel(
    const float* __restrict__ X,
    __nv_bfloat16* __restrict__ As, __nv_bfloat16* __restrict__ Bs,
    float* __restrict__ nrm)
{
    const int r = blockIdx.x, t = threadIdx.x;  // 64 threads
    float v = X[(size_t)r * DLAT + t];
    __nv_bfloat16 hi = __float2bfloat16(v);
    __nv_bfloat16 lo = __float2bfloat16(v - __bfloat162float(hi));
    size_t b = (size_t)r * 3 * DLAT;
    As[b + t] = hi; As[b + DLAT + t] = lo; As[b + 2*DLAT + t] = hi;
    Bs[b + t] = hi; Bs[b + DLAT + t] = hi; Bs[b + 2*DLAT + t] = lo;

    float s = v * v;
    #pragma unroll
    for (int o = 16; o; o >>= 1) s += __shfl_xor_sync(0xffffffffu, s, o);
    __shared__ float w2[2];
    if ((t & 31) == 0) w2[t >> 5] = s;
    __syncthreads();
    if (t == 0) nrm[r] = w2[0] + w2[1];
}

// ---------------- conversion kernels ----------------
__global__ void split_act_kernel(const float* __restrict__ x, __nv_bfloat16* __restrict__ o, int Kseg) {
    int r = blockIdx.y;
    int c = blockIdx.x * 256 + threadIdx.x;
    float v = x[(size_t)r * Kseg + c];
    __nv_bfloat16 hi = __float2bfloat16(v);
    __nv_bfloat16 lo = __float2bfloat16(v - __bfloat162float(hi));
    size_t b = (size_t)r * 3 * Kseg;
    o[b + c] = hi;
    o[b + Kseg + c] = lo;
    o[b + 2 * Kseg + c] = hi;
}

__global__ void wsplit_kernel(const float* __restrict__ W, __nv_bfloat16* __restrict__ o, int K, int N) {
    __shared__ float t[32][33];
    int n0 = blockIdx.x * 32, k0 = blockIdx.y * 32;
    int tx = threadIdx.x, ty = threadIdx.y;   // 32 x 8
    #pragma unroll
    for (int i = 0; i < 4; i++)
        t[ty + i * 8][tx] = W[(size_t)(k0 + ty + i * 8) * N + n0 + tx];
    __syncthreads();
    #pragma unroll
    for (int i = 0; i < 4; i++) {
        int n = n0 + ty + i * 8;
        float v = t[tx][ty + i * 8];
        __nv_bfloat16 hi = __float2bfloat16(v);
        __nv_bfloat16 lo = __float2bfloat16(v - __bfloat162float(hi));
        size_t b = (size_t)n * 3 * K;
        o[b + k0 + tx] = hi;
        o[b + K + k0 + tx] = hi;
        o[b + 2 * K + k0 + tx] = lo;
    }
}

// ---------------- in-place LayerNorm over 1024 ----------------
__global__ __launch_bounds__(256) void ln_inplace_kernel(
    float* __restrict__ x, const float* __restrict__ g, const float* __restrict__ b)
{
    const int row = blockIdx.x;
    float* p = x + (size_t)row * D0;
    const int tid = threadIdx.x;
    __shared__ float red[8];

    float v[4];
    float s = 0.f;
    #pragma unroll
    for (int i = 0; i < 4; i++) { v[i] = p[tid + i*256]; s += v[i]; }
    #pragma unroll
    for (int o = 16; o; o >>= 1) s += __shfl_xor_sync(0xffffffffu, s, o);
    if ((tid & 31) == 0) red[tid >> 5] = s;
    __syncthreads();
    float mu = 0.f;
    #pragma unroll
    for (int w = 0; w < 8; w++) mu += red[w];
    mu *= (1.f/1024.f);
    __syncthreads();

    float ss = 0.f;
    #pragma unroll
    for (int i = 0; i < 4; i++) { float d = v[i] - mu; ss += d*d; }
    #pragma unroll
    for (int o = 16; o; o >>= 1) ss += __shfl_xor_sync(0xffffffffu, ss, o);
    if ((tid & 31) == 0) red[tid >> 5] = ss;
    __syncthreads();
    float var = 0.f;
    #pragma unroll
    for (int w = 0; w < 8; w++) var += red[w];
    var *= (1.f/1024.f);
    float rs = rsqrtf(var + 1e-9f);

    #pragma unroll
    for (int i = 0; i < 4; i++) {
        int c = tid + i*256;
        p[c] = (v[i] - mu) * rs * g[c] + b[c];
    }
}

__global__ void zero_acc_kernel() {
    if (threadIdx.x < 3) g_acc[threadIdx.x] = 0.0;
}

__global__ void finalize_kernel(float* __restrict__ loss_out) {
    const double inv = 1.0 / ((double)NTOK * (double)NTOK);
    double mmd = (g_acc[0] + g_acc[1] - 2.0 * g_acc[2]) * inv;
    *loss_out = (float)(mmd * 64.0);
}

extern "C" void kernel_launch(void* const* d_in, const int* in_sizes, int n_in,
                              void* d_out, int out_size)
{
    const float* hidden  = (const float*)d_in[0];
    const float* true_s  = (const float*)d_in[1];
    const float* enc_w1  = (const float*)d_in[2];
    const float* enc_b1  = (const float*)d_in[3];
    const float* enc_w2  = (const float*)d_in[4];
    const float* enc_b2  = (const float*)d_in[5];
    const float* enc_lg  = (const float*)d_in[6];
    const float* enc_lb  = (const float*)d_in[7];
    const float* dec_w1  = (const float*)d_in[8];
    const float* dec_b1  = (const float*)d_in[9];
    const float* dec_w2  = (const float*)d_in[10];
    const float* dec_b2  = (const float*)d_in[11];
    const float* dec_lg  = (const float*)d_in[12];
    const float* dec_lb  = (const float*)d_in[13];

    float* recon  = (float*)d_out;                          // [4096, 1024]
    float* latent = recon + (size_t)NTOK * D0;              // [4096, 64]
    float* loss   = latent + (size_t)NTOK * DLAT;           // [1]

    __nv_bfloat16 *as, *w1s, *h1s, *w2e, *w1d, *w2s, *tsA, *tsB, *laA, *laB;
    cudaGetSymbolAddress((void**)&as,  g_as);
    cudaGetSymbolAddress((void**)&w1s, g_w1s);
    cudaGetSymbolAddress((void**)&h1s, g_h1s);
    cudaGetSymbolAddress((void**)&w2e, g_w2e);
    cudaGetSymbolAddress((void**)&w1d, g_w1d);
    cudaGetSymbolAddress((void**)&w2s, g_w2s);
    cudaGetSymbolAddress((void**)&tsA, g_tsA);
    cudaGetSymbolAddress((void**)&tsB, g_tsB);
    cudaGetSymbolAddress((void**)&laA, g_laA);
    cudaGetSymbolAddress((void**)&laB, g_laB);
    float *tn, *ln, *pp;
    cudaGetSymbolAddress((void**)&tn, g_tn);
    cudaGetSymbolAddress((void**)&ln, g_ln);
    cudaGetSymbolAddress((void**)&pp, g_p);
    double* acc; cudaGetSymbolAddress((void**)&acc, g_acc);

    const int TC_SMEM = 99328;   // 1KB align pad + 3 stages x (16KB A + 16KB B)
    const int E2_SMEM = 74752;   // 1KB pad + 3 x (16KB A + 8KB B)
    (void)cudaFuncSetAttribute(mma_gemm_kernel<0>, cudaFuncAttributeMaxDynamicSharedMemorySize, TC_SMEM);
    (void)cudaFuncSetAttribute(mma_gemm_kernel<2>, cudaFuncAttributeMaxDynamicSharedMemorySize, TC_SMEM);
    (void)cudaFuncSetAttribute(mmd_mma_kernel,     cudaFuncAttributeMaxDynamicSharedMemorySize, TC_SMEM);
    (void)cudaFuncSetAttribute(enc2_partial_kernel,cudaFuncAttributeMaxDynamicSharedMemorySize, E2_SMEM);

    zero_acc_kernel<<<1, 32>>>();

    // splits: activations + all three big weights
    split_act_kernel<<<dim3(D0/256, NTOK), 256>>>(hidden, as, D0);
    wsplit_kernel<<<dim3(DI/32, D0/32), dim3(32, 8)>>>(enc_w1, w1s, D0, DI);
    wsplit_kernel<<<dim3(DLAT/32, DI/32), dim3(32, 8)>>>(enc_w2, w2e, DI, DLAT);
    wsplit_kernel<<<dim3(DI/32, DLAT/32), dim3(32, 8)>>>(dec_w1, w1d, DLAT, DI);
    wsplit_kernel<<<dim3(D0/32, DI/32), dim3(32, 8)>>>(dec_w2, w2s, DI, D0);

    // encoder GEMM1 (HMMA, GELU, split-out) -> h1s [4096, 12288]
    mma_gemm_kernel<2><<<dim3(DI/128, NTOK/128), 256, TC_SMEM>>>(
        as, w1s, enc_b1, nullptr, h1s, 3 * D0, 0, DI);

    // encoder GEMM2 split-K (HMMA) + reduce + LN(64) -> latent
    enc2_partial_kernel<<<dim3(KSLICES, NTOK/128), 256, E2_SMEM>>>(h1s, w2e, pp);
    enc2_reduce_ln_kernel<<<NTOK, 64>>>(pp, enc_b2, enc_lg, enc_lb, latent);

    // MMD preps + terms
    mmd_prep_kernel<<<NTOK, 64>>>(true_s, tsA, tsB, tn);
    mmd_prep_kernel<<<NTOK, 64>>>(latent, laA, laB, ln);
    mmd_mma_kernel<<<dim3(NTOK/128, NTOK/128), 256, TC_SMEM>>>(tsA, tsB, tn, tn, acc + 0);
    mmd_mma_kernel<<<dim3(NTOK/128, NTOK/128), 256, TC_SMEM>>>(laA, laB, ln, ln, acc + 1);
    mmd_mma_kernel<<<dim3(NTOK/128, NTOK/128), 256, TC_SMEM>>>(tsA, laB, tn, ln, acc + 2);

    // decoder GEMM1 (HMMA, KK=192, GELU, split-out) -> h1s reuse [4096, 12288]
    mma_gemm_kernel<2><<<dim3(DI/128, NTOK/128), 256, TC_SMEM>>>(
        laA, w1d, dec_b1, nullptr, h1s, 3 * DLAT, 0, DI);

    // decoder GEMM2 (HMMA, bias only) -> recon fp32 [4096, 1024]
    mma_gemm_kernel<0><<<dim3(D0/128, NTOK/128), 256, TC_SMEM>>>(
        h1s, w2s, dec_b2, recon, nullptr, 3 * DI, D0, 0);

    // LN(1024) in place
    ln_inplace_kernel<<<NTOK, 256>>>(recon, dec_lg, dec_lb);

    finalize_kernel<<<1, 1>>>(loss);
}